// round 1
// baseline (speedup 1.0000x reference)
#include <cuda_runtime.h>
#include <cmath>

// ---------------- constants ----------------
#define LDP 68                      // shared-mem row pitch (floats): pad for banks, keeps 16B align
#define MAT (64 * LDP)              // floats per shared 64x64 matrix
#define NMAT 256
#define D64 64
#define DSQ 4096

// ---------------- device scratch (static: no allocation) ----------------
__device__ float g_logX[NMAT * DSQ];   // 4 MB
__device__ float g_B[NMAT * DSQ];      // 4 MB
__device__ float g_G[NMAT * NMAT];
__device__ float g_W[NMAT * NMAT];
__device__ float g_ssum[NMAT];
__device__ float g_rowsum[NMAT];
__device__ float g_alpha[NMAT];
__device__ float g_invrs[NMAT];

// ---------------- helpers ----------------
struct LogCoefs {
    float m[26];     // monomial coefficients of p(t) ~= log(x), t = scaleT*x - shiftT
    float scaleT;
    float shiftT;
};

// block sum over 256 threads; returns result to all threads
__device__ __forceinline__ float blockSum256(float v, float* red) {
    __syncthreads();  // protect red reuse
    int lane = threadIdx.x & 31, wid = threadIdx.x >> 5;
#pragma unroll
    for (int o = 16; o > 0; o >>= 1) v += __shfl_down_sync(0xffffffffu, v, o);
    if (lane == 0) red[wid] = v;
    __syncthreads();
    if (wid == 0) {
        v = (lane < 8) ? red[lane] : 0.f;
#pragma unroll
        for (int o = 4; o > 0; o >>= 1) v += __shfl_down_sync(0xffffffffu, v, o);
        if (lane == 0) red[0] = v;
    }
    __syncthreads();
    return red[0];
}

// C = A*B (64x64, pitch LDP). Safe when C aliases A and/or B (sync between read & write).
// Caller must have synced so A/B are valid on entry. Exits synced.
__device__ __forceinline__ void mm64(float* __restrict__ C, const float* A, const float* B, int tid) {
    const int r0 = (tid >> 4) << 2;
    const int c0 = (tid & 15) << 2;
    float4 acc0 = {0, 0, 0, 0}, acc1 = {0, 0, 0, 0}, acc2 = {0, 0, 0, 0}, acc3 = {0, 0, 0, 0};
    const float* Ar0 = A + (r0 + 0) * LDP;
    const float* Ar1 = A + (r0 + 1) * LDP;
    const float* Ar2 = A + (r0 + 2) * LDP;
    const float* Ar3 = A + (r0 + 3) * LDP;
#pragma unroll 8
    for (int k = 0; k < 64; k++) {
        float4 b = *(const float4*)(B + k * LDP + c0);
        float a0 = Ar0[k], a1 = Ar1[k], a2 = Ar2[k], a3 = Ar3[k];
        acc0.x += a0 * b.x; acc0.y += a0 * b.y; acc0.z += a0 * b.z; acc0.w += a0 * b.w;
        acc1.x += a1 * b.x; acc1.y += a1 * b.y; acc1.z += a1 * b.z; acc1.w += a1 * b.w;
        acc2.x += a2 * b.x; acc2.y += a2 * b.y; acc2.z += a2 * b.z; acc2.w += a2 * b.w;
        acc3.x += a3 * b.x; acc3.y += a3 * b.y; acc3.z += a3 * b.z; acc3.w += a3 * b.w;
    }
    __syncthreads();
    *(float4*)(C + (r0 + 0) * LDP + c0) = acc0;
    *(float4*)(C + (r0 + 1) * LDP + c0) = acc1;
    *(float4*)(C + (r0 + 2) * LDP + c0) = acc2;
    *(float4*)(C + (r0 + 3) * LDP + c0) = acc3;
    __syncthreads();
}

// ---------------- kernel 1: matrix log via Chebyshev/Paterson-Stockmeyer ----------------
// p(T) with T = scaleT*X - shiftT*I; degree 25, s=5: powers T..T^5, 4+4 matmuls.
extern "C" __global__ void __launch_bounds__(256) log_kernel(const float* __restrict__ X, LogCoefs cf) {
    extern __shared__ float sm[];
    float* P1 = sm;
    float* P2 = sm + MAT;
    float* P3 = sm + 2 * MAT;
    float* P4 = sm + 3 * MAT;
    float* P5 = sm + 4 * MAT;
    float* R  = sm + 5 * MAT;
    __shared__ float red[32];

    const int tid = threadIdx.x;
    const int n = blockIdx.x;
    const float* Xn = X + n * DSQ;

    for (int idx = tid; idx < DSQ; idx += 256) {
        int r = idx >> 6, c = idx & 63;
        float v = Xn[idx] * cf.scaleT;
        if (r == c) v -= cf.shiftT;
        P1[r * LDP + c] = v;
    }
    __syncthreads();

    mm64(P2, P1, P1, tid);
    mm64(P3, P2, P1, tid);
    mm64(P4, P2, P2, tid);
    mm64(P5, P3, P2, tid);

    // init: R = m25*T^5 + (m20 I + m21 T + m22 T^2 + m23 T^3 + m24 T^4)
    for (int idx = tid; idx < DSQ; idx += 256) {
        int r = idx >> 6, c = idx & 63;
        int o = r * LDP + c;
        float v = cf.m[25] * P5[o] + cf.m[21] * P1[o] + cf.m[22] * P2[o]
                + cf.m[23] * P3[o] + cf.m[24] * P4[o];
        if (r == c) v += cf.m[20];
        R[o] = v;
    }
    __syncthreads();

#pragma unroll
    for (int j = 3; j >= 0; j--) {
        mm64(R, R, P5, tid);   // in-place: R = R*T^5
        float b0 = cf.m[5 * j], b1 = cf.m[5 * j + 1], b2 = cf.m[5 * j + 2],
              b3 = cf.m[5 * j + 3], b4 = cf.m[5 * j + 4];
        for (int idx = tid; idx < DSQ; idx += 256) {
            int r = idx >> 6, c = idx & 63;
            int o = r * LDP + c;
            float v = b1 * P1[o] + b2 * P2[o] + b3 * P3[o] + b4 * P4[o];
            if (r == c) v += b0;
            R[o] += v;
        }
        __syncthreads();
    }

    float s = 0.f;
    for (int idx = tid; idx < DSQ; idx += 256) {
        int r = idx >> 6, c = idx & 63;
        float v = R[r * LDP + c];
        g_logX[n * DSQ + idx] = v;
        s += v;
    }
    float stot = blockSum256(s, red);
    if (tid == 0) g_ssum[n] = stot;
}

// ---------------- kernel 2: Gram matrix G = L * L^T (256x256, K=4096) ----------------
// grid (16,16), 16x16 output tile per CTA, chunked K in shared.
extern "C" __global__ void __launch_bounds__(256) gram_kernel() {
    __shared__ float sA[16 * LDP];
    __shared__ float sB[16 * LDP];
    const int tid = threadIdx.x;
    const int i0 = blockIdx.y * 16, j0 = blockIdx.x * 16;
    const int ii = tid >> 4, jj = tid & 15;
    const int lr = tid >> 4, lc = (tid & 15) << 2;

    float acc = 0.f;
    for (int kc = 0; kc < DSQ; kc += 64) {
        *(float4*)&sA[lr * LDP + lc] = *(const float4*)&g_logX[(i0 + lr) * DSQ + kc + lc];
        *(float4*)&sB[lr * LDP + lc] = *(const float4*)&g_logX[(j0 + lr) * DSQ + kc + lc];
        __syncthreads();
#pragma unroll
        for (int k = 0; k < 64; k += 4) {
            float4 av = *(const float4*)&sA[ii * LDP + k];
            float4 bv = *(const float4*)&sB[jj * LDP + k];
            acc += av.x * bv.x + av.y * bv.y + av.z * bv.z + av.w * bv.w;
        }
        __syncthreads();
    }
    g_G[(i0 + ii) * NMAT + (j0 + jj)] = acc;
}

// ---------------- kernel 3: weights W + row sums ----------------
extern "C" __global__ void __launch_bounds__(256) weight_kernel(const float* __restrict__ bwp) {
    __shared__ float red[32];
    const int i = blockIdx.x, j = threadIdx.x;
    const float bw = bwp[0];
    const float eps = 1e-7f;
    float Gii = g_G[i * NMAT + i];
    float Gjj = g_G[j * NMAT + j];
    float Gij = g_G[i * NMAT + j];
    float si = g_ssum[i], sj = g_ssum[j];
    float pds = Gii + Gjj - 2.f * Gij + 2.f * eps * (sj - si) + eps * eps * 4096.f;
    float w = expf(-0.5f * pds / (bw * bw));
    g_W[i * NMAT + j] = w;
    float rs = blockSum256(w, red);
    if (j == 0) g_rowsum[i] = rs;
}

// ---------------- kernel 3b: column sums + alpha/invrs ----------------
extern "C" __global__ void __launch_bounds__(256) colsum_kernel() {
    const int k = threadIdx.x;
    float cs = 0.f;
    for (int j = 0; j < NMAT; j++) cs += g_W[j * NMAT + k];
    float rs = g_rowsum[k];
    g_invrs[k] = 1.f / rs;
    g_alpha[k] = 1.f - cs / rs;
}

// ---------------- kernel 4: B = alpha_k*L[k] + (W^T L)[k] / rowsum_k ----------------
// grid (64 e-tiles, 4 k-tiles). 64x64 output tile, inner dim j=256 chunked by 64.
extern "C" __global__ void __launch_bounds__(256) shift_kernel() {
    __shared__ float sW[64 * LDP];  // W[j][k] chunk
    __shared__ float sL[64 * LDP];  // L[j][e] chunk
    const int tid = threadIdx.x;
    const int e0 = blockIdx.x * 64, k0 = blockIdx.y * 64;
    const int r0 = (tid >> 4) << 2;   // k-dim
    const int c0 = (tid & 15) << 2;   // e-dim

    float4 acc0 = {0, 0, 0, 0}, acc1 = {0, 0, 0, 0}, acc2 = {0, 0, 0, 0}, acc3 = {0, 0, 0, 0};
    for (int jc = 0; jc < NMAT; jc += 64) {
        for (int q = tid; q < 64 * 16; q += 256) {
            int jj = q >> 4, cc = (q & 15) << 2;
            *(float4*)&sW[jj * LDP + cc] = *(const float4*)&g_W[(jc + jj) * NMAT + k0 + cc];
            *(float4*)&sL[jj * LDP + cc] = *(const float4*)&g_logX[(jc + jj) * DSQ + e0 + cc];
        }
        __syncthreads();
#pragma unroll 4
        for (int jj = 0; jj < 64; jj++) {
            float a0 = sW[jj * LDP + r0 + 0];
            float a1 = sW[jj * LDP + r0 + 1];
            float a2 = sW[jj * LDP + r0 + 2];
            float a3 = sW[jj * LDP + r0 + 3];
            float4 b = *(const float4*)&sL[jj * LDP + c0];
            acc0.x += a0 * b.x; acc0.y += a0 * b.y; acc0.z += a0 * b.z; acc0.w += a0 * b.w;
            acc1.x += a1 * b.x; acc1.y += a1 * b.y; acc1.z += a1 * b.z; acc1.w += a1 * b.w;
            acc2.x += a2 * b.x; acc2.y += a2 * b.y; acc2.z += a2 * b.z; acc2.w += a2 * b.w;
            acc3.x += a3 * b.x; acc3.y += a3 * b.y; acc3.z += a3 * b.z; acc3.w += a3 * b.w;
        }
        __syncthreads();
    }
    float4 accs[4] = {acc0, acc1, acc2, acc3};
#pragma unroll
    for (int i = 0; i < 4; i++) {
        int k = k0 + r0 + i;
        float ir = g_invrs[k], al = g_alpha[k];
        float4 Lv = *(const float4*)&g_logX[k * DSQ + e0 + c0];
        float4 o;
        o.x = accs[i].x * ir + al * Lv.x;
        o.y = accs[i].y * ir + al * Lv.y;
        o.z = accs[i].z * ir + al * Lv.z;
        o.w = accs[i].w * ir + al * Lv.w;
        *(float4*)&g_B[k * DSQ + e0 + c0] = o;
    }
}

// ---------------- kernel 5: matrix exp via scaling & squaring + PS Taylor(12) ----------------
extern "C" __global__ void __launch_bounds__(256) exp_kernel(float* __restrict__ out) {
    extern __shared__ float sm[];
    float* S  = sm;
    float* S2 = sm + MAT;
    float* S3 = sm + 2 * MAT;
    float* R  = sm + 3 * MAT;
    __shared__ float red[32];

    const int tid = threadIdx.x;
    const int n = blockIdx.x;

    float ss = 0.f;
    for (int idx = tid; idx < DSQ; idx += 256) {
        int r = idx >> 6, c = idx & 63;
        float v = g_B[n * DSQ + idx];
        S[r * LDP + c] = v;
        ss += v * v;
    }
    float theta2 = blockSum256(ss, red);
    float theta = sqrtf(theta2);
    int kk = 0;
    float t = theta;
    while (t > 0.49f && kk < 12) { t *= 0.5f; kk++; }
    float sc = ldexpf(1.f, -kk);
    for (int idx = tid; idx < DSQ; idx += 256) {
        int r = idx >> 6, c = idx & 63;
        S[r * LDP + c] *= sc;
    }
    __syncthreads();

    mm64(S2, S, S, tid);
    mm64(S3, S2, S, tid);

    // Taylor 1/i!, i=0..12
    const float c0 = 1.f, c1 = 1.f, c2 = 0.5f, c3 = 1.f / 6.f, c4 = 1.f / 24.f, c5 = 1.f / 120.f,
                c6 = 1.f / 720.f, c7 = 1.f / 5040.f, c8 = 1.f / 40320.f, c9 = 1.f / 362880.f,
                c10 = 1.f / 3628800.f, c11 = 1.f / 39916800.f, c12 = 1.f / 479001600.f;
    const float bI[4] = {c0, c3, c6, c9};
    const float bS[4] = {c1, c4, c7, c10};
    const float bS2[4] = {c2, c5, c8, c11};

    // init: R = c12*S3 + (c9 I + c10 S + c11 S2)
    for (int idx = tid; idx < DSQ; idx += 256) {
        int r = idx >> 6, c = idx & 63;
        int o = r * LDP + c;
        float v = c12 * S3[o] + bS[3] * S[o] + bS2[3] * S2[o];
        if (r == c) v += bI[3];
        R[o] = v;
    }
    __syncthreads();
#pragma unroll
    for (int j = 2; j >= 0; j--) {
        mm64(R, R, S3, tid);
        float aI = bI[j], aS = bS[j], aS2 = bS2[j];
        for (int idx = tid; idx < DSQ; idx += 256) {
            int r = idx >> 6, c = idx & 63;
            int o = r * LDP + c;
            float v = aS * S[o] + aS2 * S2[o];
            if (r == c) v += aI;
            R[o] += v;
        }
        __syncthreads();
    }
    for (int q = 0; q < kk; q++) mm64(R, R, R, tid);  // in-place squaring

    for (int idx = tid; idx < DSQ; idx += 256) {
        int r = idx >> 6, c = idx & 63;
        out[n * DSQ + idx] = R[r * LDP + c];
    }
}

// ---------------- host: log coefficients (closed-form Chebyshev -> monomial) ----------------
static LogCoefs make_log_coefs() {
    const double a = 0.45, b = 8.0;
    const double c = 0.5 * (a + b);
    const double beta = (b - a) / (b + a);
    const double z = (std::sqrt(1.0 - beta * beta) - 1.0) / beta;  // negative, |z|<1
    double cheb[26];
    cheb[0] = std::log(c) - std::log(1.0 + z * z);
    double zk = 1.0;
    for (int k = 1; k <= 25; k++) { zk *= z; cheb[k] = -2.0 * zk / (double)k; }

    double m[26] = {0};
    double Tprev[26] = {0}, Tcur[26] = {0}, Tnext[26];
    Tprev[0] = 1.0;                        // T0
    m[0] += cheb[0];
    Tcur[1] = 1.0;                         // T1
    m[1] += cheb[1];
    for (int k = 2; k <= 25; k++) {
        for (int j = 0; j < 26; j++) Tnext[j] = -Tprev[j];
        for (int j = 0; j < 25; j++) Tnext[j + 1] += 2.0 * Tcur[j];
        for (int j = 0; j <= k; j++) m[j] += cheb[k] * Tnext[j];
        for (int j = 0; j < 26; j++) { Tprev[j] = Tcur[j]; Tcur[j] = Tnext[j]; }
    }
    LogCoefs cf;
    for (int j = 0; j < 26; j++) cf.m[j] = (float)m[j];
    cf.scaleT = (float)(2.0 / (b - a));
    cf.shiftT = (float)((a + b) / (b - a));
    return cf;
}

// ---------------- entry point ----------------
extern "C" void kernel_launch(void* const* d_in, const int* in_sizes, int n_in,
                              void* d_out, int out_size) {
    const float* X  = (const float*)d_in[0];   // [256,64,64] fp32
    const float* bw = (const float*)d_in[1];   // scalar fp32
    float* out = (float*)d_out;                // [256,64,64] fp32

    const int SMEM_LOG = 6 * MAT * (int)sizeof(float);  // 104448 B
    const int SMEM_EXP = 4 * MAT * (int)sizeof(float);  // 69632 B
    cudaFuncSetAttribute(log_kernel, cudaFuncAttributeMaxDynamicSharedMemorySize, SMEM_LOG);
    cudaFuncSetAttribute(exp_kernel, cudaFuncAttributeMaxDynamicSharedMemorySize, SMEM_EXP);

    LogCoefs cf = make_log_coefs();  // deterministic, recomputed each call

    log_kernel<<<NMAT, 256, SMEM_LOG>>>(X, cf);
    gram_kernel<<<dim3(16, 16), 256>>>();
    weight_kernel<<<NMAT, 256>>>(bw);
    colsum_kernel<<<1, 256>>>();
    shift_kernel<<<dim3(64, 4), 256>>>();
    exp_kernel<<<NMAT, 256, SMEM_EXP>>>(out);
}